// round 6
// baseline (speedup 1.0000x reference)
#include <cuda_runtime.h>
#include <cuda_bf16.h>
#include <math.h>

// ---------------- problem constants ----------------
#define MAXN 50000
#define MAXE 800000
#define D12  256

// ---------------- scratch (device globals, compile-time symbol refs only) ---
__device__ float g_bufA[MAXN * D12];   // h (post-GEMM)
__device__ float g_bufB[MAXN * D12];   // aggregated output
__device__ float g_Ab[MAXN * D12];     // pre-split GEMM A (big)
__device__ float g_As[MAXN * D12];     // pre-split GEMM A (small)
__device__ float g_Wb[256 * 256];      // pre-split GEMM B (big)
__device__ float g_Ws[256 * 256];      // pre-split GEMM B (small)
__device__ float g_als[MAXN * 4];
__device__ float g_ald[MAXN * 4];
__device__ float g_prow[MAXN * 64];
__device__ float g_pcol[MAXN * 64];
__device__ int g_deg[MAXN];
__device__ int g_off[MAXN + 1];
__device__ int g_cur[MAXN];
__device__ int g_csr[MAXE];

__device__ __forceinline__ float tf32r(float x) {
    unsigned u;
    asm("cvt.rna.tf32.f32 %0, %1;" : "=r"(u) : "f"(x));
    return __uint_as_float(u);
}

// ---------------- operand pre-split: fp32 -> (tf32 big, tf32 small) --------
// SRCEXT: true -> A source = Asrc param; false -> A source = g_bufB symbol.
template <bool SRCEXT>
__global__ void split_kernel(const float* Asrc, const float* Wsrc, int lenA4, int lenW4) {
    const float* Ap;
    if constexpr (SRCEXT) Ap = Asrc; else Ap = (const float*)g_bufB;
    int stride = gridDim.x * blockDim.x;
    int gid = blockIdx.x * blockDim.x + threadIdx.x;
    for (int i = gid; i < lenA4; i += stride) {
        float4 v = *(const float4*)(Ap + i * 4);
        float4 b, s;
        b.x = tf32r(v.x); s.x = tf32r(v.x - b.x);
        b.y = tf32r(v.y); s.y = tf32r(v.y - b.y);
        b.z = tf32r(v.z); s.z = tf32r(v.z - b.z);
        b.w = tf32r(v.w); s.w = tf32r(v.w - b.w);
        *(float4*)(g_Ab + i * 4) = b;
        *(float4*)(g_As + i * 4) = s;
    }
    for (int i = gid; i < lenW4; i += stride) {
        float4 v = *(const float4*)(Wsrc + i * 4);
        float4 b, s;
        b.x = tf32r(v.x); s.x = tf32r(v.x - b.x);
        b.y = tf32r(v.y); s.y = tf32r(v.y - b.y);
        b.z = tf32r(v.z); s.z = tf32r(v.z - b.z);
        b.w = tf32r(v.w); s.w = tf32r(v.w - b.w);
        *(float4*)(g_Wb + i * 4) = b;
        *(float4*)(g_Ws + i * 4) = s;
    }
}

// ---------------- CSR construction ----------------
__global__ void zero_deg_kernel(int n) {
    int i = blockIdx.x * blockDim.x + threadIdx.x;
    if (i < n) g_deg[i] = 0;
}

__global__ void hist_kernel(const int* ei, int E) {
    int i = blockIdx.x * blockDim.x + threadIdx.x;
    if (i < E) atomicAdd(&g_deg[ei[E + i]], 1);
}

__global__ void scan_kernel(int n) {
    __shared__ int sh[1024];
    __shared__ int s_carry;
    int tid = threadIdx.x;
    if (tid == 0) s_carry = 0;
    __syncthreads();
    for (int base = 0; base < n; base += 1024) {
        int v = (base + tid < n) ? g_deg[base + tid] : 0;
        sh[tid] = v;
        __syncthreads();
        for (int o = 1; o < 1024; o <<= 1) {
            int t2 = (tid >= o) ? sh[tid - o] : 0;
            __syncthreads();
            sh[tid] += t2;
            __syncthreads();
        }
        int incl = sh[tid];
        int c = s_carry;
        int total = sh[1023];
        if (base + tid < n) {
            int e = c + incl - v;
            g_off[base + tid] = e;
            g_cur[base + tid] = e;
        }
        __syncthreads();
        if (tid == 0) s_carry = c + total;
        __syncthreads();
    }
    if (tid == 0) g_off[n] = s_carry;
}

__global__ void scatter_kernel(const int* ei, int E) {
    int i = blockIdx.x * blockDim.x + threadIdx.x;
    if (i < E) {
        int d = ei[E + i];
        int s = ei[i];
        int p = atomicAdd(&g_cur[d], 1);
        g_csr[p] = s;
    }
}

// ---------------- 3xTF32 tensor-core GEMM (pre-split operands) -------------
// C[M,Nc] = A[M,K] @ B[K,Nc]; A = (g_Ab,g_As), B = (g_Wb,g_Ws)+boff.
// Block 128x64, BK=16, 256 threads = 8 warps (4M x 2N), warp tile 32x32.
// CSEL: 0 -> g_bufA, 1 -> g_prow, 2 -> g_pcol.

__device__ __forceinline__ void mma_tf32(float& d0, float& d1, float& d2, float& d3,
                                         float a0, float a1, float a2, float a3,
                                         float b0, float b1) {
    asm volatile(
        "mma.sync.aligned.m16n8k8.row.col.f32.tf32.tf32.f32 "
        "{%0,%1,%2,%3}, {%4,%5,%6,%7}, {%8,%9}, {%0,%1,%2,%3};"
        : "+f"(d0), "+f"(d1), "+f"(d2), "+f"(d3)
        : "r"(__float_as_uint(a0)), "r"(__float_as_uint(a1)),
          "r"(__float_as_uint(a2)), "r"(__float_as_uint(a3)),
          "r"(__float_as_uint(b0)), "r"(__float_as_uint(b1)));
}

#define A_STRIDE 20
#define B_STRIDE 68

template <int CSEL>
__global__ void gemm_tc_kernel(int boff, int M, int K, int Nc) {
    float* C;
    if constexpr (CSEL == 0) C = g_bufA;
    else if constexpr (CSEL == 1) C = g_prow;
    else C = g_pcol;

    __shared__ float sAb[128 * A_STRIDE];
    __shared__ float sAs[128 * A_STRIDE];
    __shared__ float sBb[16 * B_STRIDE];
    __shared__ float sBs[16 * B_STRIDE];

    int tid = threadIdx.x;
    int bm = blockIdx.y * 128;
    int bn = blockIdx.x * 64;
    int warpId = tid >> 5;
    int lane = tid & 31;
    int g = lane >> 2;
    int tg = lane & 3;
    int wRow = (warpId & 3) * 32;
    int wCol = (warpId >> 2) * 32;

    float d[2][4][4];
#pragma unroll
    for (int mi = 0; mi < 2; mi++)
#pragma unroll
        for (int ni = 0; ni < 4; ni++)
#pragma unroll
            for (int q = 0; q < 4; q++) d[mi][ni][q] = 0.f;

    int aIdx0 = tid * 2;
    int bIdx = tid;

    for (int k0 = 0; k0 < K; k0 += 16) {
        // stage pre-split A tile [128][16]
#pragma unroll
        for (int i = 0; i < 2; i++) {
            int fl = aIdx0 + i;
            int r = fl >> 2;
            int c4 = (fl & 3) * 4;
            float4 vb = make_float4(0.f, 0.f, 0.f, 0.f);
            float4 vs = make_float4(0.f, 0.f, 0.f, 0.f);
            if (bm + r < M) {
                size_t off = (size_t)(bm + r) * K + k0 + c4;
                vb = *(const float4*)(g_Ab + off);
                vs = *(const float4*)(g_As + off);
            }
            *(float4*)(&sAb[r * A_STRIDE + c4]) = vb;
            *(float4*)(&sAs[r * A_STRIDE + c4]) = vs;
        }
        // stage pre-split B tile [16][64]
        {
            int r = bIdx >> 4;
            int c4 = (bIdx & 15) * 4;
            size_t off = (size_t)boff + (size_t)(k0 + r) * Nc + bn + c4;
            *(float4*)(&sBb[r * B_STRIDE + c4]) = *(const float4*)(g_Wb + off);
            *(float4*)(&sBs[r * B_STRIDE + c4]) = *(const float4*)(g_Ws + off);
        }
        __syncthreads();

#pragma unroll
        for (int ks = 0; ks < 2; ks++) {
            int kc = ks * 8 + tg;
            float ab[2][4], as_[2][4];
#pragma unroll
            for (int mi = 0; mi < 2; mi++) {
                int r = wRow + mi * 16 + g;
                ab[mi][0] = sAb[r * A_STRIDE + kc];
                ab[mi][1] = sAb[(r + 8) * A_STRIDE + kc];
                ab[mi][2] = sAb[r * A_STRIDE + kc + 4];
                ab[mi][3] = sAb[(r + 8) * A_STRIDE + kc + 4];
                as_[mi][0] = sAs[r * A_STRIDE + kc];
                as_[mi][1] = sAs[(r + 8) * A_STRIDE + kc];
                as_[mi][2] = sAs[r * A_STRIDE + kc + 4];
                as_[mi][3] = sAs[(r + 8) * A_STRIDE + kc + 4];
            }
#pragma unroll
            for (int ni = 0; ni < 4; ni++) {
                int ccol = wCol + ni * 8 + g;
                float bb0 = sBb[(ks * 8 + tg) * B_STRIDE + ccol];
                float bb1 = sBb[(ks * 8 + tg + 4) * B_STRIDE + ccol];
                float bs0 = sBs[(ks * 8 + tg) * B_STRIDE + ccol];
                float bs1 = sBs[(ks * 8 + tg + 4) * B_STRIDE + ccol];
#pragma unroll
                for (int mi = 0; mi < 2; mi++) {
                    float* dd = d[mi][ni];
                    mma_tf32(dd[0], dd[1], dd[2], dd[3],
                             ab[mi][0], ab[mi][1], ab[mi][2], ab[mi][3], bb0, bb1);
                    mma_tf32(dd[0], dd[1], dd[2], dd[3],
                             ab[mi][0], ab[mi][1], ab[mi][2], ab[mi][3], bs0, bs1);
                    mma_tf32(dd[0], dd[1], dd[2], dd[3],
                             as_[mi][0], as_[mi][1], as_[mi][2], as_[mi][3], bb0, bb1);
                }
            }
        }
        __syncthreads();
    }

#pragma unroll
    for (int mi = 0; mi < 2; mi++) {
#pragma unroll
        for (int ni = 0; ni < 4; ni++) {
            int row0 = bm + wRow + mi * 16 + g;
            int col = bn + wCol + ni * 8 + tg * 2;
            if (row0 < M) {
                C[(size_t)row0 * Nc + col] = d[mi][ni][0];
                C[(size_t)row0 * Nc + col + 1] = d[mi][ni][1];
            }
            if (row0 + 8 < M) {
                C[(size_t)(row0 + 8) * Nc + col] = d[mi][ni][2];
                C[(size_t)(row0 + 8) * Nc + col + 1] = d[mi][ni][3];
            }
        }
    }
}

// ---------------- per-node attention coefficients ----------------
__global__ void al_kernel(const float* as, const float* ad, int N, int H, int C) {
    int gw = (blockIdx.x * blockDim.x + threadIdx.x) >> 5;
    int lane = threadIdx.x & 31;
    int n = gw / H;
    int hd = gw % H;
    if (n >= N) return;
    size_t base = (size_t)n * H * C + (size_t)hd * C;
    float s1 = 0.f, s2 = 0.f;
    for (int c = lane; c < C; c += 32) {
        float v = g_bufA[base + c];
        s1 = fmaf(v, as[hd * C + c], s1);
        s2 = fmaf(v, ad[hd * C + c], s2);
    }
#pragma unroll
    for (int o = 16; o; o >>= 1) {
        s1 += __shfl_down_sync(0xffffffffu, s1, o);
        s2 += __shfl_down_sync(0xffffffffu, s2, o);
    }
    if (lane == 0) {
        g_als[n * H + hd] = s1;
        g_ald[n * H + hd] = s2;
    }
}

// ---------------- GAT aggregation (block per dst node) ----------------
template <int H, int C>
__global__ void agg_kernel(const float* bias, int applyElu) {
    const int D = H * C;
    const int CHUNK = 64;
    int n = blockIdx.x;
    int t = threadIdx.x;
    __shared__ float sh_m[H];
    __shared__ float sh_iz[H];
    __shared__ float sh_alpha[CHUNK * H];
    __shared__ int sh_src[CHUNK];

    int o0 = g_off[n];
    int deg = g_off[n + 1] - o0;
    int wid = t >> 5, lane = t & 31;

    if (wid < H) {
        int hd = wid;
        float adn = g_ald[n * H + hd];
        float m = -1e30f, s = 0.f;
        for (int j = lane; j <= deg; j += 32) {
            int src = (j < deg) ? g_csr[o0 + j] : n;
            float att = g_als[src * H + hd] + adn;
            att = att > 0.f ? att : 0.2f * att;
            float mn = fmaxf(m, att);
            s = s * __expf(m - mn) + __expf(att - mn);
            m = mn;
        }
#pragma unroll
        for (int o = 16; o; o >>= 1) {
            float m2 = __shfl_down_sync(0xffffffffu, m, o);
            float s2 = __shfl_down_sync(0xffffffffu, s, o);
            float mn = fmaxf(m, m2);
            s = s * __expf(m - mn) + s2 * __expf(m2 - mn);
            m = mn;
        }
        if (lane == 0) {
            sh_m[hd] = m;
            sh_iz[hd] = 1.0f / s;
        }
    }
    __syncthreads();

    int head = t / C;
    float acc = 0.f;
    int total = deg + 1;
    for (int base = 0; base < total; base += CHUNK) {
        int cnt = min(CHUNK, total - base);
        if (t < CHUNK * H) {
            int j = t / H;
            int hd = t % H;
            if (j < cnt) {
                int src = (base + j < deg) ? g_csr[o0 + base + j] : n;
                if (hd == 0) sh_src[j] = src;
                float att = g_als[src * H + hd] + g_ald[n * H + hd];
                att = att > 0.f ? att : 0.2f * att;
                sh_alpha[j * H + hd] = __expf(att - sh_m[hd]) * sh_iz[hd];
            }
        }
        __syncthreads();
#pragma unroll 4
        for (int j = 0; j < cnt; j++) {
            acc = fmaf(g_bufA[(size_t)sh_src[j] * D + t], sh_alpha[j * H + head], acc);
        }
        __syncthreads();
    }
    float r = acc + bias[t];
    if (applyElu) r = r > 0.f ? r : expm1f(r);
    g_bufB[(size_t)n * D + t] = r;
}

// ---------------- edge MLP (warp per edge), factorized layer 1 ----------------
__global__ void edge_mlp_kernel(const int* ei, const float* ea,
                                const float* mw1, const float* mb1,
                                const float* mw2, const float* mb2,
                                const float* mw3, const float* mb3,
                                float* out, int E) {
    int warp = (int)((blockIdx.x * (size_t)blockDim.x + threadIdx.x) >> 5);
    int lane = threadIdx.x & 31;
    if (warp >= E) return;
    int row = ei[warp];
    int col = ei[E + warp];
    float ea0 = ea[warp * 2 + 0];
    float ea1 = ea[warp * 2 + 1];

    int j0 = lane, j1 = lane + 32;
    float o1a = g_prow[(size_t)row * 64 + j0] + g_pcol[(size_t)col * 64 + j0]
              + ea0 * mw1[256 * 64 + j0] + ea1 * mw1[257 * 64 + j0] + mb1[j0];
    float o1b = g_prow[(size_t)row * 64 + j1] + g_pcol[(size_t)col * 64 + j1]
              + ea0 * mw1[256 * 64 + j1] + ea1 * mw1[257 * 64 + j1] + mb1[j1];
    o1a = fmaxf(o1a, 0.f);
    o1b = fmaxf(o1b, 0.f);

    float acc = mb2[lane];
#pragma unroll
    for (int j = 0; j < 32; j++) {
        float va = __shfl_sync(0xffffffffu, o1a, j);
        float vb = __shfl_sync(0xffffffffu, o1b, j);
        acc = fmaf(va, mw2[j * 32 + lane], acc);
        acc = fmaf(vb, mw2[(j + 32) * 32 + lane], acc);
    }
    acc = fmaxf(acc, 0.f);

    float v = acc * mw3[lane];
#pragma unroll
    for (int o = 16; o; o >>= 1) v += __shfl_down_sync(0xffffffffu, v, o);
    if (lane == 0) out[warp] = v + mb3[0];
}

// ---------------- launch ----------------
extern "C" void kernel_launch(void* const* d_in, const int* in_sizes, int n_in,
                              void* d_out, int out_size) {
    const float* x = (const float*)d_in[0];
    const int* ei = (const int*)d_in[1];       // int32 (JAX demotes int64)
    const float* ea = (const float*)d_in[2];
    const float* W1 = (const float*)d_in[3];
    const float* a1s = (const float*)d_in[4];
    const float* a1d = (const float*)d_in[5];
    const float* b1 = (const float*)d_in[6];
    const float* W2 = (const float*)d_in[7];
    const float* a2s = (const float*)d_in[8];
    const float* a2d = (const float*)d_in[9];
    const float* b2 = (const float*)d_in[10];
    const float* W3 = (const float*)d_in[11];
    const float* a3s = (const float*)d_in[12];
    const float* a3d = (const float*)d_in[13];
    const float* b3 = (const float*)d_in[14];
    const float* mw1 = (const float*)d_in[15];
    const float* mb1 = (const float*)d_in[16];
    const float* mw2 = (const float*)d_in[17];
    const float* mb2 = (const float*)d_in[18];
    const float* mw3 = (const float*)d_in[19];
    const float* mb3 = (const float*)d_in[20];
    float* out = (float*)d_out;

    int N = in_sizes[0] / 32;
    int E = in_sizes[1] / 2;

    int mBlocks = (N + 127) / 128;
    dim3 g256(4, mBlocks);
    dim3 g128(2, mBlocks);
    dim3 g64(1, mBlocks);
    int alBlocks4 = ((N * 4) * 32 + 255) / 256;
    int alBlocks1 = ((N * 1) * 32 + 255) / 256;
    int splitBlocks = 592;  // grid-stride

    // 1) zero degrees
    zero_deg_kernel<<<(N + 255) / 256, 256>>>(N);
    // 2) split layer-1 operands (x, W1)
    split_kernel<true><<<splitBlocks, 256>>>(x, W1, N * 32 / 4, 32 * 256 / 4);
    // 3) histogram
    hist_kernel<<<(E + 255) / 256, 256>>>(ei, E);
    // 4) layer-1 GEMM  <-- profiled slot
    gemm_tc_kernel<0><<<g256, 256>>>(0, N, 32, 256);
    // 5) scan
    scan_kernel<<<1, 1024>>>(N);
    // 6) scatter
    scatter_kernel<<<(E + 255) / 256, 256>>>(ei, E);
    // 7-8) layer-1 attention + aggregation
    al_kernel<<<alBlocks4, 256>>>(a1s, a1d, N, 4, 64);
    agg_kernel<4, 64><<<N, 256>>>(b1, 1);

    // ---- layer 2 ----
    split_kernel<false><<<splitBlocks, 256>>>(x, W2, N * 256 / 4, 256 * 256 / 4);
    gemm_tc_kernel<0><<<g256, 256>>>(0, N, 256, 256);
    al_kernel<<<alBlocks4, 256>>>(a2s, a2d, N, 4, 64);
    agg_kernel<4, 64><<<N, 256>>>(b2, 1);

    // ---- layer 3 ----
    split_kernel<false><<<splitBlocks, 256>>>(x, W3, N * 256 / 4, 256 * 128 / 4);
    gemm_tc_kernel<0><<<g128, 256>>>(0, N, 256, 128);
    al_kernel<<<alBlocks1, 256>>>(a3s, a3d, N, 1, 128);
    agg_kernel<1, 128><<<N, 128>>>(b3, 0);

    // ---- edge MLP precompute: prow/pcol = h3 @ mw1 halves ----
    split_kernel<false><<<splitBlocks, 256>>>(x, mw1, N * 128 / 4, 256 * 64 / 4);
    gemm_tc_kernel<1><<<g64, 256>>>(0, N, 128, 64);
    gemm_tc_kernel<2><<<g64, 256>>>(128 * 64, N, 128, 64);

    // ---- edge MLP ----
    int warpsPerBlock = 8;
    int blocks = (E + warpsPerBlock - 1) / warpsPerBlock;
    edge_mlp_kernel<<<blocks, warpsPerBlock * 32>>>(ei, ea, mw1, mb1, mw2,
                                                    mb2, mw3, mb3, out, E);
}

// round 7
// speedup vs baseline: 1.1054x; 1.1054x over previous
#include <cuda_runtime.h>
#include <cuda_bf16.h>
#include <math.h>

// ---------------- problem constants ----------------
#define MAXN 50000
#define MAXE 800000
#define D12  256

// ---------------- scratch (device globals, compile-time symbol refs only) ---
__device__ float g_bufA[MAXN * D12];   // h (post-GEMM)
__device__ float g_bufB[MAXN * D12];   // aggregated output
__device__ float g_Wb[131072];         // pre-split weights (big)
__device__ float g_Ws[131072];         // pre-split weights (small)
__device__ float g_als[MAXN * 4];
__device__ float g_ald[MAXN * 4];
__device__ float g_prow[MAXN * 64];
__device__ float g_pcol[MAXN * 64];
__device__ int g_deg[MAXN];
__device__ int g_off[MAXN + 1];
__device__ int g_cur[MAXN];
__device__ int g_csr[MAXE];

// weight offsets inside g_Wb/g_Ws
#define OFF_W1   0        // 32*256   = 8192
#define OFF_W2   8192     // 256*256  = 65536
#define OFF_W3   73728    // 256*128  = 32768
#define OFF_MW1A 106496   // 128*64   = 8192
#define OFF_MW1B 114688   // 128*64   = 8192

__device__ __forceinline__ float tf32r(float x) {
    unsigned u;
    asm("cvt.rna.tf32.f32 %0, %1;" : "=r"(u) : "f"(x));
    return __uint_as_float(u);
}

// ---------------- one-time weight split (tiny) ----------------
__global__ void wsplit_kernel(const float* W1, const float* W2, const float* W3,
                              const float* mw1) {
    int stride = gridDim.x * blockDim.x;
    int gid = blockIdx.x * blockDim.x + threadIdx.x;
    // segments: (src, dstoff, len4)
    for (int seg = 0; seg < 4; seg++) {
        const float* src;
        int off, len4;
        if (seg == 0) { src = W1; off = OFF_W1; len4 = 8192 / 4; }
        else if (seg == 1) { src = W2; off = OFF_W2; len4 = 65536 / 4; }
        else if (seg == 2) { src = W3; off = OFF_W3; len4 = 32768 / 4; }
        else { src = mw1; off = OFF_MW1A; len4 = 16384 / 4; }  // mw1 rows 0..255 contiguous
        for (int i = gid; i < len4; i += stride) {
            float4 v = *(const float4*)(src + i * 4);
            float4 b, s;
            b.x = tf32r(v.x); s.x = tf32r(v.x - b.x);
            b.y = tf32r(v.y); s.y = tf32r(v.y - b.y);
            b.z = tf32r(v.z); s.z = tf32r(v.z - b.z);
            b.w = tf32r(v.w); s.w = tf32r(v.w - b.w);
            *(float4*)(g_Wb + off + i * 4) = b;
            *(float4*)(g_Ws + off + i * 4) = s;
        }
    }
}

// ---------------- CSR construction ----------------
__global__ void zero_deg_kernel(int n) {
    int i = blockIdx.x * blockDim.x + threadIdx.x;
    if (i < n) g_deg[i] = 0;
}

__global__ void hist_kernel(const int* ei, int E) {
    int i = blockIdx.x * blockDim.x + threadIdx.x;
    if (i < E) atomicAdd(&g_deg[ei[E + i]], 1);
}

__global__ void scan_kernel(int n) {
    __shared__ int sh[1024];
    __shared__ int s_carry;
    int tid = threadIdx.x;
    if (tid == 0) s_carry = 0;
    __syncthreads();
    for (int base = 0; base < n; base += 1024) {
        int v = (base + tid < n) ? g_deg[base + tid] : 0;
        sh[tid] = v;
        __syncthreads();
        for (int o = 1; o < 1024; o <<= 1) {
            int t2 = (tid >= o) ? sh[tid - o] : 0;
            __syncthreads();
            sh[tid] += t2;
            __syncthreads();
        }
        int incl = sh[tid];
        int c = s_carry;
        int total = sh[1023];
        if (base + tid < n) {
            int e = c + incl - v;
            g_off[base + tid] = e;
            g_cur[base + tid] = e;
        }
        __syncthreads();
        if (tid == 0) s_carry = c + total;
        __syncthreads();
    }
    if (tid == 0) g_off[n] = s_carry;
}

__global__ void scatter_kernel(const int* ei, int E) {
    int i = blockIdx.x * blockDim.x + threadIdx.x;
    if (i < E) {
        int d = ei[E + i];
        int s = ei[i];
        int p = atomicAdd(&g_cur[d], 1);
        g_csr[p] = s;
    }
}

// ---------------- 3xTF32 tensor-core GEMM, LDS.128 fragment loads ----------
// C[M,Nc] = A[M,K] @ B[K,Nc]; B = pre-split (g_Wb,g_Ws)+boff; A split in-kernel.
// Block 128x64, BK=16, 256 threads = 8 warps (4M x 2N), warp tile 32x32.
// smem: A [row][perm(k)] stride 20; B transposed [col][perm(k)] stride 16,
// perm(k) = (k&3)*4 + (k>>2)  ->  thread fragment = one contiguous float4.
// ASRC: 0 -> A = Aext; 1 -> A = g_bufB.
// CSEL: 0 -> g_bufA, 1 -> g_prow, 2 -> g_pcol.

__device__ __forceinline__ void mma_tf32(float& d0, float& d1, float& d2, float& d3,
                                         float a0, float a1, float a2, float a3,
                                         float b0, float b1) {
    asm volatile(
        "mma.sync.aligned.m16n8k8.row.col.f32.tf32.tf32.f32 "
        "{%0,%1,%2,%3}, {%4,%5,%6,%7}, {%8,%9}, {%0,%1,%2,%3};"
        : "+f"(d0), "+f"(d1), "+f"(d2), "+f"(d3)
        : "r"(__float_as_uint(a0)), "r"(__float_as_uint(a1)),
          "r"(__float_as_uint(a2)), "r"(__float_as_uint(a3)),
          "r"(__float_as_uint(b0)), "r"(__float_as_uint(b1)));
}

#define AS 20
#define BS 16

template <int ASRC, int CSEL>
__global__ void __launch_bounds__(256) gemm_tc_kernel(const float* Aext, int boff,
                                                      int M, int K, int Nc) {
    const float* A;
    if constexpr (ASRC == 0) A = Aext; else A = (const float*)g_bufB;
    float* C;
    if constexpr (CSEL == 0) C = g_bufA;
    else if constexpr (CSEL == 1) C = g_prow;
    else C = g_pcol;

    __shared__ float sAb[128 * AS];
    __shared__ float sAs[128 * AS];
    __shared__ float sBb[64 * BS];
    __shared__ float sBs[64 * BS];

    int tid = threadIdx.x;
    int bm = blockIdx.y * 128;
    int bn = blockIdx.x * 64;
    int warpId = tid >> 5;
    int lane = tid & 31;
    int g = lane >> 2;
    int tg = lane & 3;
    int wRow = (warpId & 3) * 32;
    int wCol = (warpId >> 2) * 32;

    // staging indices
    int ar = tid >> 1;             // A row 0..127, 2 threads per row
    int ac8 = (tid & 1) * 8;       // this thread's 8-float half of the row
    int br = tid & 15;             // B k-row 0..15
    int bc4 = (tid >> 4) * 4;      // B col group
    int bperm = (br & 3) * 4 + (br >> 2);

    float d[2][4][4];
#pragma unroll
    for (int mi = 0; mi < 2; mi++)
#pragma unroll
        for (int ni = 0; ni < 4; ni++)
#pragma unroll
            for (int q = 0; q < 4; q++) d[mi][ni][q] = 0.f;

    for (int k0 = 0; k0 < K; k0 += 16) {
        // ---- stage A: load fp32, split, store k-permuted ----
#pragma unroll
        for (int i = 0; i < 2; i++) {
            int c4 = ac8 + i * 4;
            float4 v = make_float4(0.f, 0.f, 0.f, 0.f);
            if (bm + ar < M) v = *(const float4*)(A + (size_t)(bm + ar) * K + k0 + c4);
            int base = ar * AS + (c4 >> 2);
            float b0 = tf32r(v.x), b1 = tf32r(v.y), b2 = tf32r(v.z), b3 = tf32r(v.w);
            sAb[base + 0] = b0;  sAs[base + 0] = tf32r(v.x - b0);
            sAb[base + 4] = b1;  sAs[base + 4] = tf32r(v.y - b1);
            sAb[base + 8] = b2;  sAs[base + 8] = tf32r(v.z - b2);
            sAb[base + 12] = b3; sAs[base + 12] = tf32r(v.w - b3);
        }
        // ---- stage B (pre-split): transpose + k-permute ----
        {
            size_t off = (size_t)boff + (size_t)(k0 + br) * Nc + bn + bc4;
            float4 vb = *(const float4*)(g_Wb + off);
            float4 vs = *(const float4*)(g_Ws + off);
            sBb[(bc4 + 0) * BS + bperm] = vb.x;  sBs[(bc4 + 0) * BS + bperm] = vs.x;
            sBb[(bc4 + 1) * BS + bperm] = vb.y;  sBs[(bc4 + 1) * BS + bperm] = vs.y;
            sBb[(bc4 + 2) * BS + bperm] = vb.z;  sBs[(bc4 + 2) * BS + bperm] = vs.z;
            sBb[(bc4 + 3) * BS + bperm] = vb.w;  sBs[(bc4 + 3) * BS + bperm] = vs.w;
        }
        __syncthreads();

        // ---- fragment loads: all LDS.128 ----
        float4 afb[2][2], afs[2][2];   // [mi][hi]
#pragma unroll
        for (int mi = 0; mi < 2; mi++)
#pragma unroll
            for (int hi = 0; hi < 2; hi++) {
                int row = wRow + mi * 16 + hi * 8 + g;
                afb[mi][hi] = *(const float4*)&sAb[row * AS + 4 * tg];
                afs[mi][hi] = *(const float4*)&sAs[row * AS + 4 * tg];
            }
        float4 bfb[4], bfs[4];
#pragma unroll
        for (int ni = 0; ni < 4; ni++) {
            int ccol = wCol + ni * 8 + g;
            bfb[ni] = *(const float4*)&sBb[ccol * BS + 4 * tg];
            bfs[ni] = *(const float4*)&sBs[ccol * BS + 4 * tg];
        }
        __syncthreads();

        // ---- MMAs: element q of each float4 is k = tg + 4q ----
#pragma unroll
        for (int ks = 0; ks < 2; ks++) {
#pragma unroll
            for (int ni = 0; ni < 4; ni++) {
                float bb0 = (ks == 0) ? bfb[ni].x : bfb[ni].z;
                float bb1 = (ks == 0) ? bfb[ni].y : bfb[ni].w;
                float bs0 = (ks == 0) ? bfs[ni].x : bfs[ni].z;
                float bs1 = (ks == 0) ? bfs[ni].y : bfs[ni].w;
#pragma unroll
                for (int mi = 0; mi < 2; mi++) {
                    float ab0 = (ks == 0) ? afb[mi][0].x : afb[mi][0].z;
                    float ab2 = (ks == 0) ? afb[mi][0].y : afb[mi][0].w;
                    float ab1 = (ks == 0) ? afb[mi][1].x : afb[mi][1].z;
                    float ab3 = (ks == 0) ? afb[mi][1].y : afb[mi][1].w;
                    float as0 = (ks == 0) ? afs[mi][0].x : afs[mi][0].z;
                    float as2 = (ks == 0) ? afs[mi][0].y : afs[mi][0].w;
                    float as1 = (ks == 0) ? afs[mi][1].x : afs[mi][1].z;
                    float as3 = (ks == 0) ? afs[mi][1].y : afs[mi][1].w;
                    float* dd = d[mi][ni];
                    mma_tf32(dd[0], dd[1], dd[2], dd[3], ab0, ab1, ab2, ab3, bb0, bb1);
                    mma_tf32(dd[0], dd[1], dd[2], dd[3], ab0, ab1, ab2, ab3, bs0, bs1);
                    mma_tf32(dd[0], dd[1], dd[2], dd[3], as0, as1, as2, as3, bb0, bb1);
                }
            }
        }
    }

    // ---- epilogue (float2 stores) ----
#pragma unroll
    for (int mi = 0; mi < 2; mi++) {
#pragma unroll
        for (int ni = 0; ni < 4; ni++) {
            int row0 = bm + wRow + mi * 16 + g;
            int col = bn + wCol + ni * 8 + tg * 2;
            if (row0 < M)
                *(float2*)(C + (size_t)row0 * Nc + col) = make_float2(d[mi][ni][0], d[mi][ni][1]);
            if (row0 + 8 < M)
                *(float2*)(C + (size_t)(row0 + 8) * Nc + col) = make_float2(d[mi][ni][2], d[mi][ni][3]);
        }
    }
}

// ---------------- per-node attention coefficients ----------------
__global__ void al_kernel(const float* as, const float* ad, int N, int H, int C) {
    int gw = (blockIdx.x * blockDim.x + threadIdx.x) >> 5;
    int lane = threadIdx.x & 31;
    int n = gw / H;
    int hd = gw % H;
    if (n >= N) return;
    size_t base = (size_t)n * H * C + (size_t)hd * C;
    float s1 = 0.f, s2 = 0.f;
    for (int c = lane; c < C; c += 32) {
        float v = g_bufA[base + c];
        s1 = fmaf(v, as[hd * C + c], s1);
        s2 = fmaf(v, ad[hd * C + c], s2);
    }
#pragma unroll
    for (int o = 16; o; o >>= 1) {
        s1 += __shfl_down_sync(0xffffffffu, s1, o);
        s2 += __shfl_down_sync(0xffffffffu, s2, o);
    }
    if (lane == 0) {
        g_als[n * H + hd] = s1;
        g_ald[n * H + hd] = s2;
    }
}

// ---------------- GAT aggregation, float2-vectorized -----------------------
// blockDim = H*C/2. reads g_bufA/g_als/g_ald/g_csr/g_off; writes g_bufB.
template <int H, int C>
__global__ void agg_kernel(const float* bias, int applyElu) {
    const int D2 = H * C / 2;               // threads
    const int CHUNK = (H == 4) ? 32 : 64;   // staging slots (= blockDim / H)
    int n = blockIdx.x;
    int t = threadIdx.x;
    __shared__ float sh_m[H];
    __shared__ float sh_iz[H];
    __shared__ float sh_ad[H];
    __shared__ float sh_alpha[CHUNK * H];
    __shared__ int sh_src[CHUNK];

    int o0 = g_off[n];
    int deg = g_off[n + 1] - o0;
    int wid = t >> 5, lane = t & 31;

    // pass 1: per-head online softmax stats
    if (wid < H) {
        int hd = wid;
        float adn = g_ald[n * H + hd];
        float m = -1e30f, s = 0.f;
        for (int j = lane; j <= deg; j += 32) {
            int src = (j < deg) ? g_csr[o0 + j] : n;
            float att = g_als[src * H + hd] + adn;
            att = att > 0.f ? att : 0.2f * att;
            float mn = fmaxf(m, att);
            s = s * __expf(m - mn) + __expf(att - mn);
            m = mn;
        }
#pragma unroll
        for (int o = 16; o; o >>= 1) {
            float m2 = __shfl_down_sync(0xffffffffu, m, o);
            float s2 = __shfl_down_sync(0xffffffffu, s, o);
            float mn = fmaxf(m, m2);
            s = s * __expf(m - mn) + s2 * __expf(m2 - mn);
            m = mn;
        }
        if (lane == 0) {
            sh_m[hd] = m;
            sh_iz[hd] = 1.0f / s;
            sh_ad[hd] = adn;
        }
    }
    __syncthreads();

    // pass 2: chunked alpha staging + float2 weighted accumulation
    int head = t / (C / 2);
    float2 acc = make_float2(0.f, 0.f);
    int total = deg + 1;
    const float2* h2 = (const float2*)g_bufA;
    for (int base = 0; base < total; base += CHUNK) {
        int cnt = min(CHUNK, total - base);
        {
            int j = t / H;
            int hd = t % H;
            if (j < cnt) {
                int src = (base + j < deg) ? g_csr[o0 + base + j] : n;
                if (hd == 0) sh_src[j] = src;
                float att = g_als[src * H + hd] + sh_ad[hd];
                att = att > 0.f ? att : 0.2f * att;
                sh_alpha[j * H + hd] = __expf(att - sh_m[hd]) * sh_iz[hd];
            }
        }
        __syncthreads();
#pragma unroll 4
        for (int j = 0; j < cnt; j++) {
            float2 v = h2[(size_t)sh_src[j] * D2 + t];
            float a = sh_alpha[j * H + head];
            acc.x = fmaf(v.x, a, acc.x);
            acc.y = fmaf(v.y, a, acc.y);
        }
        __syncthreads();
    }
    float rx = acc.x + bias[2 * t];
    float ry = acc.y + bias[2 * t + 1];
    if (applyElu) {
        rx = rx > 0.f ? rx : expm1f(rx);
        ry = ry > 0.f ? ry : expm1f(ry);
    }
    *(float2*)(g_bufB + (size_t)n * (2 * D2) + 2 * t) = make_float2(rx, ry);
}

// ---------------- edge MLP (warp per edge), mw2 staged in smem -------------
__global__ void edge_mlp_kernel(const int* ei, const float* ea,
                                const float* mw1, const float* mb1,
                                const float* mw2, const float* mb2,
                                const float* mw3, const float* mb3,
                                float* out, int E) {
    __shared__ float sw2[64 * 32];
    int tid = threadIdx.x;
    for (int i = tid; i < 64 * 32; i += blockDim.x) sw2[i] = mw2[i];
    __syncthreads();

    int warp = (int)((blockIdx.x * (size_t)blockDim.x + tid) >> 5);
    int lane = tid & 31;
    if (warp >= E) return;
    int row = ei[warp];
    int col = ei[E + warp];
    float ea0 = ea[warp * 2 + 0];
    float ea1 = ea[warp * 2 + 1];

    // hidden layer 1: lane handles j = 2*lane, 2*lane+1 (float2 gathers)
    int j0 = lane * 2;
    float2 pr = *(const float2*)(g_prow + (size_t)row * 64 + j0);
    float2 pc = *(const float2*)(g_pcol + (size_t)col * 64 + j0);
    float o1a = pr.x + pc.x + ea0 * mw1[256 * 64 + j0] + ea1 * mw1[257 * 64 + j0] + mb1[j0];
    float o1b = pr.y + pc.y + ea0 * mw1[256 * 64 + j0 + 1] + ea1 * mw1[257 * 64 + j0 + 1] + mb1[j0 + 1];
    o1a = fmaxf(o1a, 0.f);
    o1b = fmaxf(o1b, 0.f);

    // hidden layer 2: lane computes output k = lane
    float acc = mb2[lane];
#pragma unroll
    for (int sl = 0; sl < 32; sl++) {
        float va = __shfl_sync(0xffffffffu, o1a, sl);
        float vb = __shfl_sync(0xffffffffu, o1b, sl);
        acc = fmaf(va, sw2[(2 * sl) * 32 + lane], acc);
        acc = fmaf(vb, sw2[(2 * sl + 1) * 32 + lane], acc);
    }
    acc = fmaxf(acc, 0.f);

    // output layer
    float v = acc * mw3[lane];
#pragma unroll
    for (int o = 16; o; o >>= 1) v += __shfl_down_sync(0xffffffffu, v, o);
    if (lane == 0) out[warp] = v + mb3[0];
}

// ---------------- launch ----------------
extern "C" void kernel_launch(void* const* d_in, const int* in_sizes, int n_in,
                              void* d_out, int out_size) {
    const float* x = (const float*)d_in[0];
    const int* ei = (const int*)d_in[1];       // int32 (JAX demotes int64)
    const float* ea = (const float*)d_in[2];
    const float* W1 = (const float*)d_in[3];
    const float* a1s = (const float*)d_in[4];
    const float* a1d = (const float*)d_in[5];
    const float* b1 = (const float*)d_in[6];
    const float* W2 = (const float*)d_in[7];
    const float* a2s = (const float*)d_in[8];
    const float* a2d = (const float*)d_in[9];
    const float* b2 = (const float*)d_in[10];
    const float* W3 = (const float*)d_in[11];
    const float* a3s = (const float*)d_in[12];
    const float* a3d = (const float*)d_in[13];
    const float* b3 = (const float*)d_in[14];
    const float* mw1 = (const float*)d_in[15];
    const float* mb1 = (const float*)d_in[16];
    const float* mw2 = (const float*)d_in[17];
    const float* mb2 = (const float*)d_in[18];
    const float* mw3 = (const float*)d_in[19];
    const float* mb3 = (const float*)d_in[20];
    float* out = (float*)d_out;

    int N = in_sizes[0] / 32;
    int E = in_sizes[1] / 2;

    int mBlocks = (N + 127) / 128;
    dim3 g256(4, mBlocks);
    dim3 g128(2, mBlocks);
    dim3 g64(1, mBlocks);
    int alBlocks4 = ((N * 4) * 32 + 255) / 256;
    int alBlocks1 = ((N * 1) * 32 + 255) / 256;

    // 1) weight split (once, tiny)
    wsplit_kernel<<<120, 256>>>(W1, W2, W3, mw1);
    // 2) zero degrees
    zero_deg_kernel<<<(N + 255) / 256, 256>>>(N);
    // 3) histogram
    hist_kernel<<<(E + 255) / 256, 256>>>(ei, E);
    // 4) layer-1 GEMM  <-- profiled slot
    gemm_tc_kernel<0, 0><<<g256, 256>>>(x, OFF_W1, N, 32, 256);
    // 5) scan
    scan_kernel<<<1, 1024>>>(N);
    // 6) scatter
    scatter_kernel<<<(E + 255) / 256, 256>>>(ei, E);
    // layer-1 attention + aggregation
    al_kernel<<<alBlocks4, 256>>>(a1s, a1d, N, 4, 64);
    agg_kernel<4, 64><<<N, 128>>>(b1, 1);

    // ---- layer 2 ----
    gemm_tc_kernel<1, 0><<<g256, 256>>>(x, OFF_W2, N, 256, 256);
    al_kernel<<<alBlocks4, 256>>>(a2s, a2d, N, 4, 64);
    agg_kernel<4, 64><<<N, 128>>>(b2, 1);

    // ---- layer 3 ----
    gemm_tc_kernel<1, 0><<<g128, 256>>>(x, OFF_W3, N, 256, 128);
    al_kernel<<<alBlocks1, 256>>>(a3s, a3d, N, 1, 128);
    agg_kernel<1, 128><<<N, 64>>>(b3, 0);

    // ---- edge MLP precompute ----
    gemm_tc_kernel<1, 1><<<g64, 256>>>(x, OFF_MW1A, N, 128, 64);
    gemm_tc_kernel<1, 2><<<g64, 256>>>(x, OFF_MW1B, N, 128, 64);

    // ---- edge MLP ----
    int warpsPerBlock = 8;
    int blocks = (E + warpsPerBlock - 1) / warpsPerBlock;
    edge_mlp_kernel<<<blocks, warpsPerBlock * 32>>>(ei, ea, mw1, mb1, mw2,
                                                    mb2, mw3, mb3, out, E);
}

// round 8
// speedup vs baseline: 1.3333x; 1.2062x over previous
#include <cuda_runtime.h>
#include <cuda_bf16.h>
#include <math.h>

// ---------------- problem constants ----------------
#define MAXN 50000
#define MAXE 800000
#define D12  256

// ---------------- scratch (device globals, compile-time symbol refs only) ---
__device__ float g_bufA[MAXN * D12];       // h (post-GEMM)
__device__ float g_bufB[MAXN * D12];       // aggregated output
__device__ unsigned g_Wf[122880];          // precomputed bf16 B-fragment table
__device__ float g_als[MAXN * 4];
__device__ float g_ald[MAXN * 4];
__device__ float g_prow[MAXN * 64];
__device__ float g_pcol[MAXN * 64];
__device__ int g_deg[MAXN];
__device__ int g_off[MAXN + 1];
__device__ int g_cur[MAXN];
__device__ int g_csr[MAXE];

// fragment-table offsets (words); each weight contributes K*Nc words
#define FW1   0        // 32*256   = 8192
#define FW2   8192     // 256*256  = 65536
#define FW3   73728    // 256*128  = 32768
#define FM1A  106496   // 128*64   = 8192
#define FM1B  114688   // 128*64   = 8192

__device__ __forceinline__ unsigned pack_bf16(float lo, float hi) {
    unsigned d;
    asm("cvt.rn.bf16x2.f32 %0, %1, %2;" : "=r"(d) : "f"(hi), "f"(lo));
    return d;
}

// ---------------- one-time weight split into mma fragment layout -----------
// word index: fb + tile*1024 + (ni*32 + lane)*4 + sub
//   tile = t*nBn + bn;  sub: 0=b0 big, 1=b1 big, 2=b0 small, 3=b1 small
//   lane -> (g = lane>>2, tg = lane&3); b0 = k-pair tg, b1 = k-pair tg+4
__global__ void wsplit_kernel(const float* W1, const float* W2, const float* W3,
                              const float* mw1) {
    int w = blockIdx.x * blockDim.x + threadIdx.x;
    if (w >= 122880) return;
    const float* src;
    int Nc, nBn, rel;
    if (w < 8192)        { src = W1;            Nc = 256; nBn = 4; rel = w; }
    else if (w < 73728)  { src = W2;            Nc = 256; nBn = 4; rel = w - 8192; }
    else if (w < 106496) { src = W3;            Nc = 128; nBn = 2; rel = w - 73728; }
    else if (w < 114688) { src = mw1;           Nc = 64;  nBn = 1; rel = w - 106496; }
    else                 { src = mw1 + 128 * 64; Nc = 64; nBn = 1; rel = w - 114688; }
    int tile = rel >> 10;
    int r = rel & 1023;
    int ni = r >> 7;
    int lane = (r >> 2) & 31;
    int sub = r & 3;
    int bs = sub >> 1, bw = sub & 1;
    int g = lane >> 2, tg = lane & 3;
    int bn = tile % nBn, t = tile / nBn;
    int P = tg + bw * 4;
    int col = bn * 64 + ni * 8 + g;
    int k = t * 16 + 2 * P;
    float x0 = src[k * Nc + col];
    float x1 = src[(k + 1) * Nc + col];
    unsigned big = pack_bf16(x0, x1);
    float lo = __uint_as_float(big << 16);
    float hi = __uint_as_float(big & 0xffff0000u);
    unsigned sml = pack_bf16(x0 - lo, x1 - hi);
    g_Wf[w] = bs ? sml : big;
}

// ---------------- CSR construction ----------------
__global__ void zero_deg_kernel(int n) {
    int i = blockIdx.x * blockDim.x + threadIdx.x;
    if (i < n) g_deg[i] = 0;
}

__global__ void hist_kernel(const int* ei, int E) {
    int i = blockIdx.x * blockDim.x + threadIdx.x;
    if (i < E) atomicAdd(&g_deg[ei[E + i]], 1);
}

__global__ void scan_kernel(int n) {
    __shared__ int sh[1024];
    __shared__ int s_carry;
    int tid = threadIdx.x;
    if (tid == 0) s_carry = 0;
    __syncthreads();
    for (int base = 0; base < n; base += 1024) {
        int v = (base + tid < n) ? g_deg[base + tid] : 0;
        sh[tid] = v;
        __syncthreads();
        for (int o = 1; o < 1024; o <<= 1) {
            int t2 = (tid >= o) ? sh[tid - o] : 0;
            __syncthreads();
            sh[tid] += t2;
            __syncthreads();
        }
        int incl = sh[tid];
        int c = s_carry;
        int total = sh[1023];
        if (base + tid < n) {
            int e = c + incl - v;
            g_off[base + tid] = e;
            g_cur[base + tid] = e;
        }
        __syncthreads();
        if (tid == 0) s_carry = c + total;
        __syncthreads();
    }
    if (tid == 0) g_off[n] = s_carry;
}

__global__ void scatter_kernel(const int* ei, int E) {
    int i = blockIdx.x * blockDim.x + threadIdx.x;
    if (i < E) {
        int d = ei[E + i];
        int s = ei[i];
        int p = atomicAdd(&g_cur[d], 1);
        g_csr[p] = s;
    }
}

// ---------------- 3-term bf16 tensor-core GEMM ----------------
// C[M,Nc] = A[M,K] @ B[K,Nc];  B frags from g_Wf (precomputed), A split
// in-kernel to packed bf16 pairs in smem (fragment layout, swizzled).
// Block 128(M) x 64(N), BK=16, 256 threads = 8 warps (4M x 2N), warp 32x32.
// ASRC: 0 -> A = Aext; 1 -> A = g_bufB.
// CSEL: 0 -> g_bufA, 1 -> g_prow, 2 -> g_pcol.

__device__ __forceinline__ void mma_bf16(float& d0, float& d1, float& d2, float& d3,
                                         unsigned a0, unsigned a1, unsigned a2, unsigned a3,
                                         unsigned b0, unsigned b1) {
    asm volatile(
        "mma.sync.aligned.m16n8k16.row.col.f32.bf16.bf16.f32 "
        "{%0,%1,%2,%3}, {%4,%5,%6,%7}, {%8,%9}, {%0,%1,%2,%3};"
        : "+f"(d0), "+f"(d1), "+f"(d2), "+f"(d3)
        : "r"(a0), "r"(a1), "r"(a2), "r"(a3), "r"(b0), "r"(b1));
}

template <int ASRC, int CSEL>
__global__ void __launch_bounds__(256) gemm_bf_kernel(const float* Aext, int fbase,
                                                      int nBn, int M, int K) {
    const float* A;
    if constexpr (ASRC == 0) A = Aext; else A = (const float*)g_bufB;
    float* C;
    if constexpr (CSEL == 0) C = g_bufA;
    else if constexpr (CSEL == 1) C = g_prow;
    else C = g_pcol;
    int Nc = nBn * 64;

    __shared__ unsigned sAb[1024];
    __shared__ unsigned sAs[1024];

    int tid = threadIdx.x;
    int bm = blockIdx.y * 128;
    int bn = blockIdx.x;       // N-tile index (64 cols)
    int warpId = tid >> 5;
    int lane = tid & 31;
    int g = lane >> 2;
    int tg = lane & 3;
    int wCol = (warpId >> 2) * 32;
    int wTile0 = (warpId & 3) * 2;     // first of 2 m16 tiles for this warp

    // A staging indices: thread handles half-row (8 k) of row r
    int ar = tid >> 1;
    int khalf = tid & 1;
    int att = ar >> 4;
    int asub = ar & 15;
    int ahi = asub >> 3;
    int agg = asub & 7;

    float d[2][4][4];
#pragma unroll
    for (int mi = 0; mi < 2; mi++)
#pragma unroll
        for (int ni = 0; ni < 4; ni++)
#pragma unroll
            for (int q = 0; q < 4; q++) d[mi][ni][q] = 0.f;

    const unsigned* Wf = (const unsigned*)g_Wf;

    for (int k0 = 0; k0 < K; k0 += 16) {
        int t = k0 >> 4;
        // ---- stage A: load 8 fp32, split to bf16 big/small pair-words ----
        {
            float4 v0 = make_float4(0.f, 0.f, 0.f, 0.f);
            float4 v1 = make_float4(0.f, 0.f, 0.f, 0.f);
            if (bm + ar < M) {
                const float* p = A + (size_t)(bm + ar) * K + k0 + khalf * 8;
                v0 = *(const float4*)p;
                v1 = *(const float4*)(p + 4);
            }
            float xs[8] = {v0.x, v0.y, v0.z, v0.w, v1.x, v1.y, v1.z, v1.w};
#pragma unroll
            for (int p2 = 0; p2 < 4; p2++) {
                int tgp = p2;
                int wsl = khalf * 2 + ahi;
                int slot = tgp ^ ((agg >> 1) & 3);
                int idx = att * 128 + (agg * 4 + slot) * 4 + wsl;
                unsigned big = pack_bf16(xs[2 * p2], xs[2 * p2 + 1]);
                float lo = __uint_as_float(big << 16);
                float hi = __uint_as_float(big & 0xffff0000u);
                sAb[idx] = big;
                sAs[idx] = pack_bf16(xs[2 * p2] - lo, xs[2 * p2 + 1] - hi);
            }
        }
        // ---- B fragments straight from global (L2-hot, coalesced) ----
        uint4 bfr[4];
        {
            const uint4* fb = (const uint4*)(Wf + fbase + (size_t)(t * nBn + bn) * 1024);
#pragma unroll
            for (int nj = 0; nj < 4; nj++)
                bfr[nj] = fb[((wCol >> 3) + nj) * 32 + lane];
        }
        __syncthreads();

        // ---- A fragments: one LDS.128 per (tile, big/small) ----
        uint4 afb[2], afs[2];
#pragma unroll
        for (int mi = 0; mi < 2; mi++) {
            int base = (wTile0 + mi) * 128 + (g * 4 + (tg ^ ((g >> 1) & 3))) * 4;
            afb[mi] = *(const uint4*)&sAb[base];
            afs[mi] = *(const uint4*)&sAs[base];
        }
        __syncthreads();

        // ---- MMAs: Ab*Bb + Ab*Bs + As*Bb ----
#pragma unroll
        for (int ni = 0; ni < 4; ni++) {
            uint4 b = bfr[ni];
#pragma unroll
            for (int mi = 0; mi < 2; mi++) {
                float* dd = d[mi][ni];
                mma_bf16(dd[0], dd[1], dd[2], dd[3],
                         afb[mi].x, afb[mi].y, afb[mi].z, afb[mi].w, b.x, b.y);
                mma_bf16(dd[0], dd[1], dd[2], dd[3],
                         afb[mi].x, afb[mi].y, afb[mi].z, afb[mi].w, b.z, b.w);
                mma_bf16(dd[0], dd[1], dd[2], dd[3],
                         afs[mi].x, afs[mi].y, afs[mi].z, afs[mi].w, b.x, b.y);
            }
        }
    }

    // ---- epilogue (float2 stores) ----
#pragma unroll
    for (int mi = 0; mi < 2; mi++) {
#pragma unroll
        for (int ni = 0; ni < 4; ni++) {
            int row0 = bm + (wTile0 + mi) * 16 + g;
            int col = bn * 64 + wCol + ni * 8 + tg * 2;
            if (row0 < M)
                *(float2*)(C + (size_t)row0 * Nc + col) = make_float2(d[mi][ni][0], d[mi][ni][1]);
            if (row0 + 8 < M)
                *(float2*)(C + (size_t)(row0 + 8) * Nc + col) = make_float2(d[mi][ni][2], d[mi][ni][3]);
        }
    }
}

// ---------------- per-node attention coefficients ----------------
__global__ void al_kernel(const float* as, const float* ad, int N, int H, int C) {
    int gw = (blockIdx.x * blockDim.x + threadIdx.x) >> 5;
    int lane = threadIdx.x & 31;
    int n = gw / H;
    int hd = gw % H;
    if (n >= N) return;
    size_t base = (size_t)n * H * C + (size_t)hd * C;
    float s1 = 0.f, s2 = 0.f;
    for (int c = lane; c < C; c += 32) {
        float v = g_bufA[base + c];
        s1 = fmaf(v, as[hd * C + c], s1);
        s2 = fmaf(v, ad[hd * C + c], s2);
    }
#pragma unroll
    for (int o = 16; o; o >>= 1) {
        s1 += __shfl_down_sync(0xffffffffu, s1, o);
        s2 += __shfl_down_sync(0xffffffffu, s2, o);
    }
    if (lane == 0) {
        g_als[n * H + hd] = s1;
        g_ald[n * H + hd] = s2;
    }
}

// ---------------- GAT aggregation, float2-vectorized -----------------------
template <int H, int C>
__global__ void agg_kernel(const float* bias, int applyElu) {
    const int D2 = H * C / 2;
    const int CHUNK = (H == 4) ? 32 : 64;
    int n = blockIdx.x;
    int t = threadIdx.x;
    __shared__ float sh_m[H];
    __shared__ float sh_iz[H];
    __shared__ float sh_ad[H];
    __shared__ float sh_alpha[CHUNK * H];
    __shared__ int sh_src[CHUNK];

    int o0 = g_off[n];
    int deg = g_off[n + 1] - o0;
    int wid = t >> 5, lane = t & 31;

    if (wid < H) {
        int hd = wid;
        float adn = g_ald[n * H + hd];
        float m = -1e30f, s = 0.f;
        for (int j = lane; j <= deg; j += 32) {
            int src = (j < deg) ? g_csr[o0 + j] : n;
            float att = g_als[src * H + hd] + adn;
            att = att > 0.f ? att : 0.2f * att;
            float mn = fmaxf(m, att);
            s = s * __expf(m - mn) + __expf(att - mn);
            m = mn;
        }
#pragma unroll
        for (int o = 16; o; o >>= 1) {
            float m2 = __shfl_down_sync(0xffffffffu, m, o);
            float s2 = __shfl_down_sync(0xffffffffu, s, o);
            float mn = fmaxf(m, m2);
            s = s * __expf(m - mn) + s2 * __expf(m2 - mn);
            m = mn;
        }
        if (lane == 0) {
            sh_m[hd] = m;
            sh_iz[hd] = 1.0f / s;
            sh_ad[hd] = adn;
        }
    }
    __syncthreads();

    int head = t / (C / 2);
    float2 acc = make_float2(0.f, 0.f);
    int total = deg + 1;
    const float2* h2 = (const float2*)g_bufA;
    for (int base = 0; base < total; base += CHUNK) {
        int cnt = min(CHUNK, total - base);
        {
            int j = t / H;
            int hd = t % H;
            if (j < cnt) {
                int src = (base + j < deg) ? g_csr[o0 + base + j] : n;
                if (hd == 0) sh_src[j] = src;
                float att = g_als[src * H + hd] + sh_ad[hd];
                att = att > 0.f ? att : 0.2f * att;
                sh_alpha[j * H + hd] = __expf(att - sh_m[hd]) * sh_iz[hd];
            }
        }
        __syncthreads();
#pragma unroll 4
        for (int j = 0; j < cnt; j++) {
            float2 v = h2[(size_t)sh_src[j] * D2 + t];
            float a = sh_alpha[j * H + head];
            acc.x = fmaf(v.x, a, acc.x);
            acc.y = fmaf(v.y, a, acc.y);
        }
        __syncthreads();
    }
    float rx = acc.x + bias[2 * t];
    float ry = acc.y + bias[2 * t + 1];
    if (applyElu) {
        rx = rx > 0.f ? rx : expm1f(rx);
        ry = ry > 0.f ? ry : expm1f(ry);
    }
    *(float2*)(g_bufB + (size_t)n * (2 * D2) + 2 * t) = make_float2(rx, ry);
}

// ---------------- edge MLP (warp per edge), 1024-thread blocks -------------
__global__ void __launch_bounds__(1024) edge_mlp_kernel(const int* ei, const float* ea,
                                const float* mw1, const float* mb1,
                                const float* mw2, const float* mb2,
                                const float* mw3, const float* mb3,
                                float* out, int E) {
    __shared__ float sw2[64 * 32];
    int tid = threadIdx.x;
    for (int i = tid; i < 64 * 32; i += 1024) sw2[i] = mw2[i];
    __syncthreads();

    int warp = (int)((blockIdx.x * (size_t)blockDim.x + tid) >> 5);
    int lane = tid & 31;
    if (warp >= E) return;
    int row = ei[warp];
    int col = ei[E + warp];
    float ea0 = ea[warp * 2 + 0];
    float ea1 = ea[warp * 2 + 1];

    int j0 = lane * 2;
    float2 pr = *(const float2*)(g_prow + (size_t)row * 64 + j0);
    float2 pc = *(const float2*)(g_pcol + (size_t)col * 64 + j0);
    float o1a = pr.x + pc.x + ea0 * mw1[256 * 64 + j0] + ea1 * mw1[257 * 64 + j0] + mb1[j0];
    float o1b = pr.y + pc.y + ea0 * mw1[256 * 64 + j0 + 1] + ea1 * mw1[257 * 64 + j0 + 1] + mb1[j0 + 1];
    o1a = fmaxf(o1a, 0.f);
    o1b = fmaxf(o1b, 0.f);

    float acc = mb2[lane];
#pragma unroll
    for (int sl = 0; sl < 32; sl++) {
        float va = __shfl_sync(0xffffffffu, o1a, sl);
        float vb = __shfl_sync(0xffffffffu, o1b, sl);
        acc = fmaf(va, sw2[(2 * sl) * 32 + lane], acc);
        acc = fmaf(vb, sw2[(2 * sl + 1) * 32 + lane], acc);
    }
    acc = fmaxf(acc, 0.f);

    float v = acc * mw3[lane];
#pragma unroll
    for (int o = 16; o; o >>= 1) v += __shfl_down_sync(0xffffffffu, v, o);
    if (lane == 0) out[warp] = v + mb3[0];
}

// ---------------- launch ----------------
extern "C" void kernel_launch(void* const* d_in, const int* in_sizes, int n_in,
                              void* d_out, int out_size) {
    const float* x = (const float*)d_in[0];
    const int* ei = (const int*)d_in[1];       // int32 (JAX demotes int64)
    const float* ea = (const float*)d_in[2];
    const float* W1 = (const float*)d_in[3];
    const float* a1s = (const float*)d_in[4];
    const float* a1d = (const float*)d_in[5];
    const float* b1 = (const float*)d_in[6];
    const float* W2 = (const float*)d_in[7];
    const float* a2s = (const float*)d_in[8];
    const float* a2d = (const float*)d_in[9];
    const float* b2 = (const float*)d_in[10];
    const float* W3 = (const float*)d_in[11];
    const float* a3s = (const float*)d_in[12];
    const float* a3d = (const float*)d_in[13];
    const float* b3 = (const float*)d_in[14];
    const float* mw1 = (const float*)d_in[15];
    const float* mb1 = (const float*)d_in[16];
    const float* mw2 = (const float*)d_in[17];
    const float* mb2 = (const float*)d_in[18];
    const float* mw3 = (const float*)d_in[19];
    const float* mb3 = (const float*)d_in[20];
    float* out = (float*)d_out;

    int N = in_sizes[0] / 32;
    int E = in_sizes[1] / 2;

    int mBlocks = (N + 127) / 128;
    dim3 g256(4, mBlocks);
    dim3 g128(2, mBlocks);
    dim3 g64(1, mBlocks);
    int alBlocks4 = ((N * 4) * 32 + 255) / 256;
    int alBlocks1 = ((N * 1) * 32 + 255) / 256;

    // 1) weight split into fragment table (once, tiny)
    wsplit_kernel<<<480, 256>>>(W1, W2, W3, mw1);
    // 2) zero degrees
    zero_deg_kernel<<<(N + 255) / 256, 256>>>(N);
    // 3) histogram
    hist_kernel<<<(E + 255) / 256, 256>>>(ei, E);
    // 4) layer-1 GEMM  <-- profiled slot
    gemm_bf_kernel<0, 0><<<g256, 256>>>(x, FW1, 4, N, 32);
    // 5) scan
    scan_kernel<<<1, 1024>>>(N);
    // 6) scatter
    scatter_kernel<<<(E + 255) / 256, 256>>>(ei, E);
    // layer-1 attention + aggregation
    al_kernel<<<alBlocks4, 256>>>(a1s, a1d, N, 4, 64);
    agg_kernel<4, 64><<<N, 128>>>(b1, 1);

    // ---- layer 2 ----
    gemm_bf_kernel<1, 0><<<g256, 256>>>(x, FW2, 4, N, 256);
    al_kernel<<<alBlocks4, 256>>>(a2s, a2d, N, 4, 64);
    agg_kernel<4, 64><<<N, 128>>>(b2, 1);

    // ---- layer 3 ----
    gemm_bf_kernel<1, 0><<<g128, 256>>>(x, FW3, 2, N, 256);
    al_kernel<<<alBlocks1, 256>>>(a3s, a3d, N, 1, 128);
    agg_kernel<1, 128><<<N, 64>>>(b3, 0);

    // ---- edge MLP precompute ----
    gemm_bf_kernel<1, 1><<<g64, 256>>>(x, FM1A, 1, N, 128);
    gemm_bf_kernel<1, 2><<<g64, 256>>>(x, FM1B, 1, N, 128);

    // ---- edge MLP ----
    int blocks = (E + 31) / 32;
    edge_mlp_kernel<<<blocks, 1024>>>(ei, ea, mw1, mb1, mw2, mb2, mw3, mb3, out, E);
}